// round 3
// baseline (speedup 1.0000x reference)
#include <cuda_runtime.h>
#include <cstddef>

// ---------------------------------------------------------------------------
// Problem constants
// ---------------------------------------------------------------------------
#define HH    128
#define WWID  128
#define HW    16384            // 128*128
#define NB    4
#define CCH   64
#define NCHW  4194304          // 4*64*16384
#define WSZ   102400           // 64*25*64

// ---------------------------------------------------------------------------
// Scratch: __device__ globals (module-load allocation; no cudaMalloc)
// ---------------------------------------------------------------------------
__device__ float g_A[NCHW];                 // ping
__device__ float g_B[NCHW];                 // pong
__device__ float g_T[4ull * NCHW];          // t0..t3 (t3 never read)
__device__ float g_wf[3 * WSZ];             // fwd  weights [l][ci][ky][kx][co]
__device__ float g_wb[3 * WSZ];             // bwd  weights [l][cin][ky][kx][cout] (flipped)
__device__ float g_w0[25 * 64];             // conv0 weights [ky][kx][co]
__device__ float g_w0b[64 * 25];            // final convT weights [a][ky][kx] (flipped)
__device__ float g_actp[4 * 64 * 80];       // padded act tables: [l][c][80], data at +8

// ---------------------------------------------------------------------------
// RBF mixture activation, windowed (|k|<=6) stable recurrence.
//   f(v) = sum_p w[p] exp(-(v-mu_p)^2/200),  mu_p = -310 + 10 p
//   p0 = nearest center, d0 = v - mu_p0
//   exp(-(d0-10k)^2/200) = E0 * a^k * e^{-k^2/2},  E0 = e^{-d0^2/200}, a=e^{d0/10}
// wrow points at p=0 of a zero-padded row (8 left / 9 right) -> branch free.
// ---------------------------------------------------------------------------
__device__ __forceinline__ float act_fwd(float v, const float* __restrict__ wrow) {
    float pf = rintf((v + 310.f) * 0.1f);
    pf = fminf(fmaxf(pf, 0.f), 62.f);
    float d0 = v + 310.f - 10.f * pf;
    d0 = fminf(fmaxf(d0, -55.f), 55.f);
    float a  = __expf(0.1f * d0);
    float ai = __expf(-0.1f * d0);
    float E0 = __expf(-0.005f * d0 * d0);
    const float* w = wrow + (int)pf;
    const float CK[7] = {0.f, 0.60653066f, 0.22313016f, 0.082084999f,
                         0.030197383f, 0.011108997f, 0.0040867714f};
    float s = w[0];
    float up = 1.f, un = 1.f;
#pragma unroll
    for (int k = 1; k <= 6; k++) {
        up *= a  * CK[k];
        un *= ai * CK[k];
        s += w[k] * up + w[-k] * un;
    }
    return E0 * s;
}

// f'(v) = -(1/100) * E0 * (d0*s - 10*s1),  s1 = sum_k k w_k u_k
__device__ __forceinline__ float act_grad(float v, const float* __restrict__ wrow) {
    float pf = rintf((v + 310.f) * 0.1f);
    pf = fminf(fmaxf(pf, 0.f), 62.f);
    float d0 = v + 310.f - 10.f * pf;
    d0 = fminf(fmaxf(d0, -55.f), 55.f);
    float a  = __expf(0.1f * d0);
    float ai = __expf(-0.1f * d0);
    float E0 = __expf(-0.005f * d0 * d0);
    const float* w = wrow + (int)pf;
    const float CK[7] = {0.f, 0.60653066f, 0.22313016f, 0.082084999f,
                         0.030197383f, 0.011108997f, 0.0040867714f};
    float s = w[0], s1 = 0.f;
    float up = 1.f, un = 1.f;
#pragma unroll
    for (int k = 1; k <= 6; k++) {
        up *= a  * CK[k];
        un *= ai * CK[k];
        float tp = w[k]  * up;
        float tm = w[-k] * un;
        s  += tp + tm;
        s1 += (float)k * (tp - tm);
    }
    return -0.01f * E0 * (d0 * s - 10.f * s1);
}

// ---------------------------------------------------------------------------
// Weight / table prep
// ---------------------------------------------------------------------------
__global__ void prep_kernel(const float* __restrict__ f0,
                            const float* __restrict__ fr,
                            const float* __restrict__ actw) {
    int idx = blockIdx.x * 256 + threadIdx.x;
    if (idx < 3 * WSZ) {
        int co = idx & 63;
        int r  = idx >> 6;
        int kx = r % 5; r /= 5;
        int ky = r % 5; r /= 5;
        int ci = r & 63;
        int l  = r >> 6;
        // fwd: wf[l][ci][ky][kx][co] = fr[l][co][ci][ky][kx]
        g_wf[idx] = fr[(((l * 64 + co) * 64 + ci) * 25) + ky * 5 + kx];
        // bwd (conv_t as zero-padded corr): wb[l][a][ky][kx][b] = fr[l][a][b][4-ky][4-kx]
        g_wb[idx] = fr[(((l * 64 + ci) * 64 + co) * 25) + (4 - ky) * 5 + (4 - kx)];
    }
    if (idx < 1600) {
        int co = idx & 63;
        int r  = idx >> 6;
        int kx = r % 5, ky = r / 5;
        g_w0[idx] = f0[co * 25 + ky * 5 + kx];           // [ky][kx][co]
        int a = idx / 25, q = idx % 25;
        int u = q / 5, v = q % 5;
        g_w0b[idx] = f0[a * 25 + (4 - u) * 5 + (4 - v)]; // [a][u][v], flipped
    }
    if (idx < 4 * 64 * 80) {
        int q  = (idx % 80) - 8;
        int lc = idx / 80;
        g_actp[idx] = (q >= 0 && q < 63) ? actw[lc * 63 + q] : 0.f;
    }
}

// ---------------------------------------------------------------------------
// Main conv kernel. Tile 32x8 px, 256 threads; thread = 8 px (y) x 8 co.
// FWD (BWD=false): replication pad, +bias, store conv (tout) and act (out).
// BWD (BWD=true):  zero pad, epilogue gate by act_grad(tg), store to out.
// Weights: [ci][u][v][co] co-fastest -> warp-uniform float4 LDG (broadcast).
// ---------------------------------------------------------------------------
template <bool BWD>
__global__ __launch_bounds__(256, 2)
void conv_kernel(const float* __restrict__ in, int nci, float inscale,
                 const float* __restrict__ w,
                 const float* __restrict__ bias,
                 const float* __restrict__ actp,
                 const float* __restrict__ tg,
                 float* __restrict__ tout,
                 float* __restrict__ out) {
    __shared__ float s_act[64 * 80];
    __shared__ float s_in[12 * 36];
    const int tid = threadIdx.x;
    const int x   = tid & 31;
    const int wid = tid >> 5;                  // co octet
    const int n   = blockIdx.z;
    const int tx0 = blockIdx.x * 32, ty0 = blockIdx.y * 8;

    for (int i = tid; i < 64 * 80; i += 256) s_act[i] = actp[i];

    float acc[64];
#pragma unroll
    for (int i = 0; i < 64; i++) acc[i] = 0.f;

    for (int ci = 0; ci < nci; ci++) {
        __syncthreads();                        // also covers s_act on first iter
        const float* ip = in + ((size_t)(n * nci + ci)) * HW;
        for (int i = tid; i < 432; i += 256) {
            int py = i / 36, px = i - py * 36;
            int gy = ty0 + py - 2, gx = tx0 + px - 2;
            float v;
            if (BWD) {
                v = (gy >= 0 && gy < 128 && gx >= 0 && gx < 128) ? ip[gy * 128 + gx] : 0.f;
            } else {
                gy = min(max(gy, 0), 127);
                gx = min(max(gx, 0), 127);
                v = ip[gy * 128 + gx] * inscale;
            }
            s_in[i] = v;
        }
        __syncthreads();
        const float* wp = w + ci * 1600 + wid * 8;
#pragma unroll
        for (int u = 0; u < 5; u++) {
#pragma unroll
            for (int v = 0; v < 5; v++) {
                const float4* wq = reinterpret_cast<const float4*>(wp + (u * 5 + v) * 64);
                float4 wa = __ldg(wq);
                float4 wb = __ldg(wq + 1);
#pragma unroll
                for (int yy = 0; yy < 8; yy++) {
                    float iv = s_in[(yy + u) * 36 + x + v];
                    acc[yy * 8 + 0] += iv * wa.x;
                    acc[yy * 8 + 1] += iv * wa.y;
                    acc[yy * 8 + 2] += iv * wa.z;
                    acc[yy * 8 + 3] += iv * wa.w;
                    acc[yy * 8 + 4] += iv * wb.x;
                    acc[yy * 8 + 5] += iv * wb.y;
                    acc[yy * 8 + 6] += iv * wb.z;
                    acc[yy * 8 + 7] += iv * wb.w;
                }
            }
        }
    }

    // Epilogue
#pragma unroll
    for (int c = 0; c < 8; c++) {
        const int co = wid * 8 + c;
        const float* wrow = &s_act[co * 80 + 8];
        const float b = BWD ? 0.f : bias[co];
        size_t base = ((size_t)(n * 64 + co)) * HW + (size_t)ty0 * 128 + tx0 + x;
#pragma unroll
        for (int yy = 0; yy < 8; yy++) {
            size_t idx = base + (size_t)yy * 128;
            float v = acc[yy * 8 + c] + b;
            if (BWD) {
                float tv = tg[idx];
                out[idx] = v * act_grad(tv, wrow);
            } else {
                tout[idx] = v;
                out[idx]  = act_fwd(v, wrow);
            }
        }
    }
}

// ---------------------------------------------------------------------------
// Final: r = crop(conv_t(in, f0)) (64->1, zero pad), out = x - r/255 - e^lam*(x-y)
// ---------------------------------------------------------------------------
__global__ __launch_bounds__(256)
void final_kernel(const float* __restrict__ in,
                  const float* __restrict__ xin,
                  const float* __restrict__ yin,
                  const float* __restrict__ lam,
                  float* __restrict__ out) {
    __shared__ float s_w[1600];
    __shared__ float s_in[12 * 36];
    const int tid = threadIdx.x;
    const int x   = tid & 31;
    const int yy  = tid >> 5;
    const int n   = blockIdx.z;
    const int tx0 = blockIdx.x * 32, ty0 = blockIdx.y * 8;

    for (int i = tid; i < 1600; i += 256) s_w[i] = g_w0b[i];

    float acc = 0.f;
    for (int a = 0; a < 64; a++) {
        __syncthreads();
        const float* ip = in + ((size_t)(n * 64 + a)) * HW;
        for (int i = tid; i < 432; i += 256) {
            int py = i / 36, px = i - py * 36;
            int gy = ty0 + py - 2, gx = tx0 + px - 2;
            s_in[i] = (gy >= 0 && gy < 128 && gx >= 0 && gx < 128) ? ip[gy * 128 + gx] : 0.f;
        }
        __syncthreads();
        const float* wp = &s_w[a * 25];
#pragma unroll
        for (int u = 0; u < 5; u++)
#pragma unroll
            for (int v = 0; v < 5; v++)
                acc += s_in[(yy + u) * 36 + x + v] * wp[u * 5 + v];
    }
    size_t idx = (size_t)n * HW + (size_t)(ty0 + yy) * 128 + tx0 + x;
    float xv = xin[idx], yv = yin[idx];
    float el = __expf(lam[0]);
    out[idx] = xv - acc * (1.f / 255.f) - el * (xv - yv);
}

// ---------------------------------------------------------------------------
// Launch
// ---------------------------------------------------------------------------
extern "C" void kernel_launch(void* const* d_in, const int* in_sizes, int n_in,
                              void* d_out, int out_size) {
    const float *x = nullptr, *y = nullptr, *lam = nullptr, *f0 = nullptr,
                *fr = nullptr, *bias = nullptr, *actw = nullptr;
    for (int i = 0; i < n_in; i++) {
        const float* p = (const float*)d_in[i];
        switch (in_sizes[i]) {
            case 65536: if (!x) x = p; else y = p; break;   // x first, y second (metadata order)
            case 1:      lam  = p; break;
            case 1600:   f0   = p; break;
            case 307200: fr   = p; break;
            case 256:    bias = p; break;
            case 16128:  actw = p; break;
            default: break;
        }
    }

    void *pA, *pB, *pT, *pwf, *pwb, *pw0, *pact;
    cudaGetSymbolAddress(&pA, g_A);
    cudaGetSymbolAddress(&pB, g_B);
    cudaGetSymbolAddress(&pT, g_T);
    cudaGetSymbolAddress(&pwf, g_wf);
    cudaGetSymbolAddress(&pwb, g_wb);
    cudaGetSymbolAddress(&pw0, g_w0);
    cudaGetSymbolAddress(&pact, g_actp);
    float* A   = (float*)pA;
    float* B   = (float*)pB;
    float* T   = (float*)pT;
    float* wf  = (float*)pwf;
    float* wb  = (float*)pwb;
    float* w0  = (float*)pw0;
    float* act = (float*)pact;

    dim3 grid(4, 16, 4), blk(256);

    prep_kernel<<<1200, 256>>>(f0, fr, actw);

    // forward: conv0 (1->64, x255) then layers 1..3
    conv_kernel<false><<<grid, blk>>>(x, 1,  255.f, w0,           bias,       act,            nullptr,          T,                A);
    conv_kernel<false><<<grid, blk>>>(A, 64, 1.f,   wf,           bias + 64,  act + 5120,     nullptr,          T + (size_t)NCHW, B);
    conv_kernel<false><<<grid, blk>>>(B, 64, 1.f,   wf + WSZ,     bias + 128, act + 2 * 5120, nullptr,          T + 2ull * NCHW,  A);
    conv_kernel<false><<<grid, blk>>>(A, 64, 1.f,   wf + 2 * WSZ, bias + 192, act + 3 * 5120, nullptr,          T + 3ull * NCHW,  B);

    // backward: convT(l) with act_grad(t_{l-1}) gate fused in epilogue
    conv_kernel<true><<<grid, blk>>>(B, 64, 1.f, wb + 2 * WSZ, nullptr, act + 2 * 5120, T + 2ull * NCHW,  nullptr, A);
    conv_kernel<true><<<grid, blk>>>(A, 64, 1.f, wb + WSZ,     nullptr, act + 5120,     T + (size_t)NCHW, nullptr, B);
    conv_kernel<true><<<grid, blk>>>(B, 64, 1.f, wb,           nullptr, act,            T,                nullptr, A);

    // final convT (64->1) + combine
    final_kernel<<<grid, blk>>>(A, x, y, lam, (float*)d_out);
}